// round 1
// baseline (speedup 1.0000x reference)
#include <cuda_runtime.h>
#include <math.h>
#include <stdint.h>

#define N_CELLS 16384
#define H 512
#define D 512
#define KNB 15

// ---------------- scratch (__device__ globals; no allocation in kernel_launch) ----
__device__ float g_ur [N_CELLS * H];   // unit real of rotated state
__device__ float g_ui [N_CELLS * H];   // unit imag
__device__ float g_mag[N_CELLS * H];   // magnitude
__device__ float g_new_re[N_CELLS * H];
__device__ float g_new_im[N_CELLS * H];
__device__ int    g_lasing[N_CELLS];
__device__ int    g_nlasing;
__device__ float  g_em_re[H];
__device__ float  g_em_im[H];
__device__ float  g_cavn_re[H];
__device__ float  g_cavn_im[H];
__device__ float  g_cav_phase[H];
__device__ double g_sum, g_sum2;

// ---------------- K0: zero accumulators ----------------
__global__ void k_init() {
    int t = threadIdx.x;
    if (t < H) { g_em_re[t] = 0.f; g_em_im[t] = 0.f; }
    if (t == 0) { g_nlasing = 0; g_sum = 0.0; g_sum2 = 0.0; }
}

// ---------------- K1: pump -> excited -> lasing mask ----------------
// one warp per cell; 256 threads = 8 cells/block
__global__ void k_pump(const float* __restrict__ x,
                       const float* __restrict__ W,
                       const float* __restrict__ b,
                       const float* __restrict__ excited) {
    int gwarp = (blockIdx.x * blockDim.x + threadIdx.x) >> 5;
    int lane  = threadIdx.x & 31;
    if (gwarp >= N_CELLS) return;
    const float* w = W + (size_t)gwarp * D;
    float s = 0.f;
#pragma unroll
    for (int t = 0; t < D / 32; t++)
        s += x[lane + 32 * t] * w[lane + 32 * t];
#pragma unroll
    for (int o = 16; o; o >>= 1) s += __shfl_xor_sync(0xFFFFFFFFu, s, o);
    if (lane == 0) {
        float z = s + b[gwarp];
        float pump = 1.f / (1.f + expf(-z));
        float e = excited[gwarp] * 0.95f + pump * 0.05f;
        e = fminf(fmaxf(e, 0.f), 1.f);
        int las = (e > 0.5f) ? 1 : 0;
        g_lasing[gwarp] = las;
        if (las) atomicAdd(&g_nlasing, 1);
    }
}

// ---------------- K2: free phase rotation + polar decomposition ----------------
__global__ void k_rot(const float* __restrict__ cr,
                      const float* __restrict__ ci,
                      const float* __restrict__ pv) {
    int i = blockIdx.x * blockDim.x + threadIdx.x;
    if (i >= N_CELLS * H) return;
    float sn, cs;
    __sincosf(0.1f * pv[i], &sn, &cs);
    float a = cr[i], b = ci[i];
    float re = a * cs - b * sn;
    float im = a * sn + b * cs;
    float m2 = re * re + im * im;
    float inv = rsqrtf(fmaxf(m2, 1e-30f));
    g_ur[i]  = re * inv;
    g_ui[i]  = im * inv;
    g_mag[i] = m2 * inv;   // = |s|
}

// ---------------- K3: neighbor phase coupling (hot kernel) ----------------
// block = one cell; 128 threads x 4 channels (float4)
// coupling = cos(ang_i - ang_j) = u_i . u_j  ->  contribution = (u_i.u_j)*mag_j*u_j
// new = 0.7*s_i + (0.3*0.1/15) * sum_j contribution
__global__ void __launch_bounds__(128) k_couple(const int* __restrict__ nbr) {
    int cell = blockIdx.x;
    int t = threadIdx.x;
    __shared__ int snb[KNB];
    if (t < KNB) snb[t] = nbr[cell * KNB + t];
    __syncthreads();

    size_t base = (size_t)cell * H + (size_t)t * 4;
    float4 ur = *(const float4*)(g_ur  + base);
    float4 ui = *(const float4*)(g_ui  + base);
    float4 mg = *(const float4*)(g_mag + base);

    float ar0 = 0.f, ar1 = 0.f, ar2 = 0.f, ar3 = 0.f;
    float ai0 = 0.f, ai1 = 0.f, ai2 = 0.f, ai3 = 0.f;

#pragma unroll 1
    for (int j = 0; j < KNB; j++) {
        size_t nb = (size_t)snb[j] * H + (size_t)t * 4;
        float4 nur = *(const float4*)(g_ur  + nb);
        float4 nui = *(const float4*)(g_ui  + nb);
        float4 nmg = *(const float4*)(g_mag + nb);

        float d, tt;
        d = fmaf(ur.x, nur.x, ui.x * nui.x); tt = d * nmg.x;
        ar0 = fmaf(tt, nur.x, ar0); ai0 = fmaf(tt, nui.x, ai0);
        d = fmaf(ur.y, nur.y, ui.y * nui.y); tt = d * nmg.y;
        ar1 = fmaf(tt, nur.y, ar1); ai1 = fmaf(tt, nui.y, ai1);
        d = fmaf(ur.z, nur.z, ui.z * nui.z); tt = d * nmg.z;
        ar2 = fmaf(tt, nur.z, ar2); ai2 = fmaf(tt, nui.z, ai2);
        d = fmaf(ur.w, nur.w, ui.w * nui.w); tt = d * nmg.w;
        ar3 = fmaf(tt, nur.w, ar3); ai3 = fmaf(tt, nui.w, ai3);
    }

    const float CF = 0.3f * 0.1f / (float)KNB;  // 0.002
    float4 outre, outim;
    outre.x = 0.7f * mg.x * ur.x + CF * ar0;
    outre.y = 0.7f * mg.y * ur.y + CF * ar1;
    outre.z = 0.7f * mg.z * ur.z + CF * ar2;
    outre.w = 0.7f * mg.w * ur.w + CF * ar3;
    outim.x = 0.7f * mg.x * ui.x + CF * ai0;
    outim.y = 0.7f * mg.y * ui.y + CF * ai1;
    outim.z = 0.7f * mg.z * ui.z + CF * ai2;
    outim.w = 0.7f * mg.w * ui.w + CF * ai3;

    *(float4*)(g_new_re + base) = outre;
    *(float4*)(g_new_im + base) = outim;
}

// ---------------- K4: emission = sum over lasing cells of new_states ----------------
// 256 blocks x 64 cells; 128 threads x 4 channels
__global__ void __launch_bounds__(128) k_emit() {
    int t = threadIdx.x;
    int c0 = blockIdx.x * 64;
    float sr0 = 0, sr1 = 0, sr2 = 0, sr3 = 0, si0 = 0, si1 = 0, si2 = 0, si3 = 0;
    for (int c = 0; c < 64; c++) {
        int cell = c0 + c;
        if (g_lasing[cell]) {
            size_t base = (size_t)cell * H + (size_t)t * 4;
            float4 r = *(const float4*)(g_new_re + base);
            float4 i = *(const float4*)(g_new_im + base);
            sr0 += r.x; sr1 += r.y; sr2 += r.z; sr3 += r.w;
            si0 += i.x; si1 += i.y; si2 += i.z; si3 += i.w;
        }
    }
    int h = t * 4;
    atomicAdd(&g_em_re[h + 0], sr0); atomicAdd(&g_em_re[h + 1], sr1);
    atomicAdd(&g_em_re[h + 2], sr2); atomicAdd(&g_em_re[h + 3], sr3);
    atomicAdd(&g_em_im[h + 0], si0); atomicAdd(&g_em_im[h + 1], si1);
    atomicAdd(&g_em_im[h + 2], si2); atomicAdd(&g_em_im[h + 3], si3);
}

// ---------------- K5: cavity update + decode GEMV ----------------
__global__ void __launch_bounds__(512) k_cav(const float* __restrict__ cav_re,
                                             const float* __restrict__ cav_im,
                                             const float* __restrict__ decW,
                                             const float* __restrict__ decb,
                                             float* __restrict__ out) {
    __shared__ float sv[2 * H];
    int t = threadIdx.x;  // 512
    int nl = g_nlasing;
    float inv = 1.f / fmaxf((float)nl, 1.f);
    float cr = cav_re[t], ci = cav_im[t];
    float nr = (nl > 0) ? 0.8f * cr + 0.2f * (g_em_re[t] * inv) : cr;
    float ni = (nl > 0) ? 0.8f * ci + 0.2f * (g_em_im[t] * inv) : ci;
    g_cavn_re[t] = nr;
    g_cavn_im[t] = ni;
    g_cav_phase[t] = atan2f(ci, cr);   // OLD cavity phase
    sv[t] = nr;
    sv[H + t] = ni;
    __syncthreads();
    float acc = decb[t];
    const float* w = decW + (size_t)t * 2 * H;
#pragma unroll 8
    for (int j = 0; j < 2 * H; j++) acc = fmaf(sv[j], w[j], acc);
    out[t] = acc;
}

// ---------------- K6: phase lock + feedback + renorm + variance accum ----------------
__global__ void __launch_bounds__(128) k_final() {
    int cell = blockIdx.x;
    int t = threadIdx.x;  // 128
    __shared__ float red[128];
    __shared__ float rs[128], rs2[128];

    size_t base = (size_t)cell * H + (size_t)t * 4;
    float4 r4 = *(const float4*)(g_new_re + base);
    float4 i4 = *(const float4*)(g_new_im + base);
    int las = g_lasing[cell];

    float vr[4], vi[4], amp[4];
    float re_[4] = {r4.x, r4.y, r4.z, r4.w};
    float im_[4] = {i4.x, i4.y, i4.z, i4.w};
    float mx = 0.f;
#pragma unroll
    for (int q = 0; q < 4; q++) {
        int h = t * 4 + q;
        float re = re_[q], im = im_[q];
        if (las) {
            float a = sqrtf(re * re + im * im);
            float ang = 0.3f * g_cav_phase[h] + 0.7f * atan2f(im, re);
            float sn, cs;
            __sincosf(ang, &sn, &cs);
            re = a * cs;
            im = a * sn;
        }
        re += 0.05f * g_cavn_re[h];
        im += 0.05f * g_cavn_im[h];
        vr[q] = re; vi[q] = im;
        amp[q] = sqrtf(re * re + im * im);
        mx = fmaxf(mx, amp[q]);
    }
    red[t] = mx;
    __syncthreads();
#pragma unroll
    for (int o = 64; o; o >>= 1) {
        if (t < o) red[t] = fmaxf(red[t], red[t + o]);
        __syncthreads();
    }
    float inv = 1.f / (red[0] + 1e-8f);
    float s = 0.f, s2 = 0.f;
#pragma unroll
    for (int q = 0; q < 4; q++) {
        float an = amp[q] * inv;
        s += an;
        s2 = fmaf(an, an, s2);
    }
    rs[t] = s; rs2[t] = s2;
    __syncthreads();
#pragma unroll
    for (int o = 64; o; o >>= 1) {
        if (t < o) { rs[t] += rs[t + o]; rs2[t] += rs2[t + o]; }
        __syncthreads();
    }
    if (t == 0) {
        atomicAdd(&g_sum,  (double)rs[0]);
        atomicAdd(&g_sum2, (double)rs2[0]);
    }
}

// ---------------- K7: tension ----------------
__global__ void k_tension(float* __restrict__ out, int out_size) {
    double M = (double)N_CELLS * (double)H;
    double mean = g_sum / M;
    double var = g_sum2 / M - mean * mean;
    out[out_size - 1] = (float)var;
}

// ---------------- launcher ----------------
extern "C" void kernel_launch(void* const* d_in, const int* in_sizes, int n_in,
                              void* d_out, int out_size) {
    const float* x       = (const float*)d_in[0];
    const float* pump_W  = (const float*)d_in[1];
    const float* pump_b  = (const float*)d_in[2];
    const float* dec_W   = (const float*)d_in[3];
    const float* dec_b   = (const float*)d_in[4];
    const float* cs_re   = (const float*)d_in[5];
    const float* cs_im   = (const float*)d_in[6];
    const float* excited = (const float*)d_in[7];
    const float* phase_v = (const float*)d_in[8];
    const float* cav_re  = (const float*)d_in[9];
    const float* cav_im  = (const float*)d_in[10];
    const int*   nbr     = (const int*)d_in[11];
    float* out = (float*)d_out;

    k_init<<<1, H>>>();
    k_pump<<<(N_CELLS * 32) / 256, 256>>>(x, pump_W, pump_b, excited);
    k_rot<<<(N_CELLS * H) / 256, 256>>>(cs_re, cs_im, phase_v);
    k_couple<<<N_CELLS, 128>>>(nbr);
    k_emit<<<N_CELLS / 64, 128>>>();
    k_cav<<<1, 512>>>(cav_re, cav_im, dec_W, dec_b, out);
    k_final<<<N_CELLS, 128>>>();
    k_tension<<<1, 1>>>(out, out_size);
}

// round 2
// speedup vs baseline: 2.4006x; 2.4006x over previous
#include <cuda_runtime.h>
#include <math.h>
#include <stdint.h>

#define N_CELLS 16384
#define H 512
#define D 512
#define KNB 15

// ---------------- scratch (__device__ globals; no allocation in kernel_launch) ----
__device__ float g_ur [N_CELLS * H];   // unit real of rotated state
__device__ float g_ui [N_CELLS * H];   // unit imag
__device__ float g_mag[N_CELLS * H];   // magnitude
__device__ float g_new_re[N_CELLS * H];
__device__ float g_new_im[N_CELLS * H];
__device__ int    g_lasing[N_CELLS];
__device__ int    g_nlasing;
__device__ float  g_em_re[H];
__device__ float  g_em_im[H];
__device__ float  g_cavn_re[H];
__device__ float  g_cavn_im[H];
__device__ float  g_cav_phase[H];
__device__ double g_sum, g_sum2;

// ---------------- K0: zero accumulators ----------------
__global__ void k_init() {
    int t = threadIdx.x;
    if (t < H) { g_em_re[t] = 0.f; g_em_im[t] = 0.f; }
    if (t == 0) { g_nlasing = 0; g_sum = 0.0; g_sum2 = 0.0; }
}

// ---------------- K1: pump -> excited -> lasing mask ----------------
__global__ void k_pump(const float* __restrict__ x,
                       const float* __restrict__ W,
                       const float* __restrict__ b,
                       const float* __restrict__ excited) {
    int gwarp = (blockIdx.x * blockDim.x + threadIdx.x) >> 5;
    int lane  = threadIdx.x & 31;
    if (gwarp >= N_CELLS) return;
    const float* w = W + (size_t)gwarp * D;
    float s = 0.f;
#pragma unroll
    for (int t = 0; t < D / 32; t++)
        s += x[lane + 32 * t] * w[lane + 32 * t];
#pragma unroll
    for (int o = 16; o; o >>= 1) s += __shfl_xor_sync(0xFFFFFFFFu, s, o);
    if (lane == 0) {
        float z = s + b[gwarp];
        float pump = 1.f / (1.f + expf(-z));
        float e = excited[gwarp] * 0.95f + pump * 0.05f;
        e = fminf(fmaxf(e, 0.f), 1.f);
        int las = (e > 0.5f) ? 1 : 0;
        g_lasing[gwarp] = las;
        if (las) atomicAdd(&g_nlasing, 1);
    }
}

// ---------------- K2: free phase rotation + polar decomposition ----------------
__global__ void k_rot(const float* __restrict__ cr,
                      const float* __restrict__ ci,
                      const float* __restrict__ pv) {
    int i = blockIdx.x * blockDim.x + threadIdx.x;
    if (i >= N_CELLS * H) return;
    float sn, cs;
    __sincosf(0.1f * pv[i], &sn, &cs);
    float a = cr[i], b = ci[i];
    float re = a * cs - b * sn;
    float im = a * sn + b * cs;
    float m2 = re * re + im * im;
    float inv = rsqrtf(fmaxf(m2, 1e-30f));
    g_ur[i]  = re * inv;
    g_ui[i]  = im * inv;
    g_mag[i] = m2 * inv;   // = |s|
}

// ---------------- K3: neighbor phase coupling (hot kernel) ----------------
__global__ void __launch_bounds__(128) k_couple(const int* __restrict__ nbr) {
    int cell = blockIdx.x;
    int t = threadIdx.x;
    __shared__ int snb[KNB];
    if (t < KNB) snb[t] = nbr[cell * KNB + t];
    __syncthreads();

    size_t base = (size_t)cell * H + (size_t)t * 4;
    float4 ur = *(const float4*)(g_ur  + base);
    float4 ui = *(const float4*)(g_ui  + base);
    float4 mg = *(const float4*)(g_mag + base);

    float ar0 = 0.f, ar1 = 0.f, ar2 = 0.f, ar3 = 0.f;
    float ai0 = 0.f, ai1 = 0.f, ai2 = 0.f, ai3 = 0.f;

#pragma unroll 1
    for (int j = 0; j < KNB; j++) {
        size_t nb = (size_t)snb[j] * H + (size_t)t * 4;
        float4 nur = *(const float4*)(g_ur  + nb);
        float4 nui = *(const float4*)(g_ui  + nb);
        float4 nmg = *(const float4*)(g_mag + nb);

        float d, tt;
        d = fmaf(ur.x, nur.x, ui.x * nui.x); tt = d * nmg.x;
        ar0 = fmaf(tt, nur.x, ar0); ai0 = fmaf(tt, nui.x, ai0);
        d = fmaf(ur.y, nur.y, ui.y * nui.y); tt = d * nmg.y;
        ar1 = fmaf(tt, nur.y, ar1); ai1 = fmaf(tt, nui.y, ai1);
        d = fmaf(ur.z, nur.z, ui.z * nui.z); tt = d * nmg.z;
        ar2 = fmaf(tt, nur.z, ar2); ai2 = fmaf(tt, nui.z, ai2);
        d = fmaf(ur.w, nur.w, ui.w * nui.w); tt = d * nmg.w;
        ar3 = fmaf(tt, nur.w, ar3); ai3 = fmaf(tt, nui.w, ai3);
    }

    const float CF = 0.3f * 0.1f / (float)KNB;  // 0.002
    float4 outre, outim;
    outre.x = 0.7f * mg.x * ur.x + CF * ar0;
    outre.y = 0.7f * mg.y * ur.y + CF * ar1;
    outre.z = 0.7f * mg.z * ur.z + CF * ar2;
    outre.w = 0.7f * mg.w * ur.w + CF * ar3;
    outim.x = 0.7f * mg.x * ui.x + CF * ai0;
    outim.y = 0.7f * mg.y * ui.y + CF * ai1;
    outim.z = 0.7f * mg.z * ui.z + CF * ai2;
    outim.w = 0.7f * mg.w * ui.w + CF * ai3;

    *(float4*)(g_new_re + base) = outre;
    *(float4*)(g_new_im + base) = outim;
}

// ---------------- K4: emission = sum over lasing cells of new_states ----------------
__global__ void __launch_bounds__(128) k_emit() {
    int t = threadIdx.x;
    int c0 = blockIdx.x * 64;
    float sr0 = 0, sr1 = 0, sr2 = 0, sr3 = 0, si0 = 0, si1 = 0, si2 = 0, si3 = 0;
    for (int c = 0; c < 64; c++) {
        int cell = c0 + c;
        if (g_lasing[cell]) {
            size_t base = (size_t)cell * H + (size_t)t * 4;
            float4 r = *(const float4*)(g_new_re + base);
            float4 i = *(const float4*)(g_new_im + base);
            sr0 += r.x; sr1 += r.y; sr2 += r.z; sr3 += r.w;
            si0 += i.x; si1 += i.y; si2 += i.z; si3 += i.w;
        }
    }
    int h = t * 4;
    atomicAdd(&g_em_re[h + 0], sr0); atomicAdd(&g_em_re[h + 1], sr1);
    atomicAdd(&g_em_re[h + 2], sr2); atomicAdd(&g_em_re[h + 3], sr3);
    atomicAdd(&g_em_im[h + 0], si0); atomicAdd(&g_em_im[h + 1], si1);
    atomicAdd(&g_em_im[h + 2], si2); atomicAdd(&g_em_im[h + 3], si3);
}

// ---------------- K5a: cavity update only (tiny, 1 block) ----------------
__global__ void __launch_bounds__(512) k_cav_update(const float* __restrict__ cav_re,
                                                    const float* __restrict__ cav_im) {
    int t = threadIdx.x;  // 512
    int nl = g_nlasing;
    float inv = 1.f / fmaxf((float)nl, 1.f);
    float cr = cav_re[t], ci = cav_im[t];
    float nr = (nl > 0) ? 0.8f * cr + 0.2f * (g_em_re[t] * inv) : cr;
    float ni = (nl > 0) ? 0.8f * ci + 0.2f * (g_em_im[t] * inv) : ci;
    g_cavn_re[t] = nr;
    g_cavn_im[t] = ni;
    g_cav_phase[t] = atan2f(ci, cr);   // OLD cavity phase
}

// ---------------- K5b: decode GEMV, one block per output, coalesced ----------------
__global__ void __launch_bounds__(128) k_decode(const float* __restrict__ decW,
                                                const float* __restrict__ decb,
                                                float* __restrict__ out) {
    int d = blockIdx.x;           // 0..511
    int t = threadIdx.x;          // 128
    const float* w = decW + (size_t)d * (2 * H);
    float s = 0.f;
#pragma unroll
    for (int j = t; j < 2 * H; j += 128) {
        float v = (j < H) ? g_cavn_re[j] : g_cavn_im[j - H];
        s = fmaf(v, w[j], s);
    }
#pragma unroll
    for (int o = 16; o; o >>= 1) s += __shfl_xor_sync(0xFFFFFFFFu, s, o);
    __shared__ float red[4];
    if ((t & 31) == 0) red[t >> 5] = s;
    __syncthreads();
    if (t == 0) out[d] = red[0] + red[1] + red[2] + red[3] + decb[d];
}

// ---------------- K6: phase lock + feedback + renorm + variance accum ----------------
__global__ void __launch_bounds__(128) k_final() {
    int cell = blockIdx.x;
    int t = threadIdx.x;  // 128
    __shared__ float red[128];
    __shared__ float rs[128], rs2[128];

    size_t base = (size_t)cell * H + (size_t)t * 4;
    float4 r4 = *(const float4*)(g_new_re + base);
    float4 i4 = *(const float4*)(g_new_im + base);
    int las = g_lasing[cell];

    float amp[4];
    float re_[4] = {r4.x, r4.y, r4.z, r4.w};
    float im_[4] = {i4.x, i4.y, i4.z, i4.w};
    float mx = 0.f;
#pragma unroll
    for (int q = 0; q < 4; q++) {
        int h = t * 4 + q;
        float re = re_[q], im = im_[q];
        if (las) {
            float a = sqrtf(re * re + im * im);
            float ang = 0.3f * g_cav_phase[h] + 0.7f * atan2f(im, re);
            float sn, cs;
            __sincosf(ang, &sn, &cs);
            re = a * cs;
            im = a * sn;
        }
        re += 0.05f * g_cavn_re[h];
        im += 0.05f * g_cavn_im[h];
        amp[q] = sqrtf(re * re + im * im);
        mx = fmaxf(mx, amp[q]);
    }
    red[t] = mx;
    __syncthreads();
#pragma unroll
    for (int o = 64; o; o >>= 1) {
        if (t < o) red[t] = fmaxf(red[t], red[t + o]);
        __syncthreads();
    }
    float inv = 1.f / (red[0] + 1e-8f);
    float s = 0.f, s2 = 0.f;
#pragma unroll
    for (int q = 0; q < 4; q++) {
        float an = amp[q] * inv;
        s += an;
        s2 = fmaf(an, an, s2);
    }
    rs[t] = s; rs2[t] = s2;
    __syncthreads();
#pragma unroll
    for (int o = 64; o; o >>= 1) {
        if (t < o) { rs[t] += rs[t + o]; rs2[t] += rs2[t + o]; }
        __syncthreads();
    }
    if (t == 0) {
        atomicAdd(&g_sum,  (double)rs[0]);
        atomicAdd(&g_sum2, (double)rs2[0]);
    }
}

// ---------------- K7: tension ----------------
__global__ void k_tension(float* __restrict__ out, int out_size) {
    double M = (double)N_CELLS * (double)H;
    double mean = g_sum / M;
    double var = g_sum2 / M - mean * mean;
    out[out_size - 1] = (float)var;
}

// ---------------- launcher ----------------
extern "C" void kernel_launch(void* const* d_in, const int* in_sizes, int n_in,
                              void* d_out, int out_size) {
    const float* x       = (const float*)d_in[0];
    const float* pump_W  = (const float*)d_in[1];
    const float* pump_b  = (const float*)d_in[2];
    const float* dec_W   = (const float*)d_in[3];
    const float* dec_b   = (const float*)d_in[4];
    const float* cs_re   = (const float*)d_in[5];
    const float* cs_im   = (const float*)d_in[6];
    const float* excited = (const float*)d_in[7];
    const float* phase_v = (const float*)d_in[8];
    const float* cav_re  = (const float*)d_in[9];
    const float* cav_im  = (const float*)d_in[10];
    const int*   nbr     = (const int*)d_in[11];
    float* out = (float*)d_out;

    k_init<<<1, H>>>();
    k_pump<<<(N_CELLS * 32) / 256, 256>>>(x, pump_W, pump_b, excited);
    k_rot<<<(N_CELLS * H) / 256, 256>>>(cs_re, cs_im, phase_v);
    k_couple<<<N_CELLS, 128>>>(nbr);
    k_emit<<<N_CELLS / 64, 128>>>();
    k_cav_update<<<1, 512>>>(cav_re, cav_im);
    k_decode<<<D, 128>>>(dec_W, dec_b, out);
    k_final<<<N_CELLS, 128>>>();
    k_tension<<<1, 1>>>(out, out_size);
}

// round 3
// speedup vs baseline: 2.7040x; 1.1264x over previous
#include <cuda_runtime.h>
#include <cuda_fp16.h>
#include <math.h>
#include <stdint.h>

#define N_CELLS 16384
#define H 512
#define D 512
#define KNB 15

// ---------------- scratch ----------------
__device__ __half2 g_u  [N_CELLS * H];   // packed unit vector (re,im) of rotated state
__device__ float   g_mag[N_CELLS * H];   // magnitude
__device__ float g_new_re[N_CELLS * H];
__device__ float g_new_im[N_CELLS * H];
__device__ int    g_lasing[N_CELLS];
__device__ int    g_nlasing;
__device__ float  g_em_re[H];
__device__ float  g_em_im[H];
__device__ float  g_cavn_re[H];
__device__ float  g_cavn_im[H];
__device__ float  g_cav_phase[H];
__device__ double g_sum, g_sum2;

// ---------------- K0 ----------------
__global__ void k_init() {
    int t = threadIdx.x;
    if (t < H) { g_em_re[t] = 0.f; g_em_im[t] = 0.f; }
    if (t == 0) { g_nlasing = 0; g_sum = 0.0; g_sum2 = 0.0; }
}

// ---------------- K1: pump -> lasing ----------------
__global__ void k_pump(const float* __restrict__ x,
                       const float* __restrict__ W,
                       const float* __restrict__ b,
                       const float* __restrict__ excited) {
    int gwarp = (blockIdx.x * blockDim.x + threadIdx.x) >> 5;
    int lane  = threadIdx.x & 31;
    if (gwarp >= N_CELLS) return;
    const float* w = W + (size_t)gwarp * D;
    float s = 0.f;
#pragma unroll
    for (int t = 0; t < D / 32; t++)
        s += x[lane + 32 * t] * w[lane + 32 * t];
#pragma unroll
    for (int o = 16; o; o >>= 1) s += __shfl_xor_sync(0xFFFFFFFFu, s, o);
    if (lane == 0) {
        float z = s + b[gwarp];
        float pump = 1.f / (1.f + expf(-z));
        float e = excited[gwarp] * 0.95f + pump * 0.05f;
        e = fminf(fmaxf(e, 0.f), 1.f);
        int las = (e > 0.5f) ? 1 : 0;
        g_lasing[gwarp] = las;
        if (las) atomicAdd(&g_nlasing, 1);
    }
}

// ---------------- K2: rotate + polar decompose (packed) ----------------
__global__ void k_rot(const float* __restrict__ cr,
                      const float* __restrict__ ci,
                      const float* __restrict__ pv) {
    int i = blockIdx.x * blockDim.x + threadIdx.x;
    if (i >= N_CELLS * H) return;
    float sn, cs;
    __sincosf(0.1f * pv[i], &sn, &cs);
    float a = cr[i], b = ci[i];
    float re = a * cs - b * sn;
    float im = a * sn + b * cs;
    float m2 = re * re + im * im;
    float inv = rsqrtf(fmaxf(m2, 1e-30f));
    g_u[i]   = __floats2half2_rn(re * inv, im * inv);
    g_mag[i] = m2 * inv;   // = |s|
}

// ---------------- K3: neighbor coupling (hot) ----------------
// contribution_j = (u_i . u_j) * mag_j * u_j ; new = 0.7*s_i + 0.002 * sum_j
__global__ void __launch_bounds__(128) k_couple(const int* __restrict__ nbr) {
    int cell = blockIdx.x;
    int t = threadIdx.x;
    __shared__ int snb[KNB];
    if (t < KNB) snb[t] = nbr[cell * KNB + t];
    __syncthreads();

    size_t base = (size_t)cell * H + (size_t)t * 4;

    // own u (4 channels) + mag
    uint4 up = *(const uint4*)(g_u + base);
    float4 mg = *(const float4*)(g_mag + base);
    float2 u0 = __half22float2(*(const __half2*)&up.x);
    float2 u1 = __half22float2(*(const __half2*)&up.y);
    float2 u2 = __half22float2(*(const __half2*)&up.z);
    float2 u3 = __half22float2(*(const __half2*)&up.w);

    float ar0 = 0.f, ar1 = 0.f, ar2 = 0.f, ar3 = 0.f;
    float ai0 = 0.f, ai1 = 0.f, ai2 = 0.f, ai3 = 0.f;

#pragma unroll 1
    for (int j = 0; j < KNB; j++) {
        size_t nb = (size_t)snb[j] * H + (size_t)t * 4;
        uint4  nup = *(const uint4*)(g_u + nb);
        float4 nmg = *(const float4*)(g_mag + nb);
        float2 n0 = __half22float2(*(const __half2*)&nup.x);
        float2 n1 = __half22float2(*(const __half2*)&nup.y);
        float2 n2 = __half22float2(*(const __half2*)&nup.z);
        float2 n3 = __half22float2(*(const __half2*)&nup.w);

        float d, tt;
        d = fmaf(u0.x, n0.x, u0.y * n0.y); tt = d * nmg.x;
        ar0 = fmaf(tt, n0.x, ar0); ai0 = fmaf(tt, n0.y, ai0);
        d = fmaf(u1.x, n1.x, u1.y * n1.y); tt = d * nmg.y;
        ar1 = fmaf(tt, n1.x, ar1); ai1 = fmaf(tt, n1.y, ai1);
        d = fmaf(u2.x, n2.x, u2.y * n2.y); tt = d * nmg.z;
        ar2 = fmaf(tt, n2.x, ar2); ai2 = fmaf(tt, n2.y, ai2);
        d = fmaf(u3.x, n3.x, u3.y * n3.y); tt = d * nmg.w;
        ar3 = fmaf(tt, n3.x, ar3); ai3 = fmaf(tt, n3.y, ai3);
    }

    const float CF = 0.3f * 0.1f / (float)KNB;  // 0.002
    float4 outre, outim;
    outre.x = 0.7f * mg.x * u0.x + CF * ar0;
    outre.y = 0.7f * mg.y * u1.x + CF * ar1;
    outre.z = 0.7f * mg.z * u2.x + CF * ar2;
    outre.w = 0.7f * mg.w * u3.x + CF * ar3;
    outim.x = 0.7f * mg.x * u0.y + CF * ai0;
    outim.y = 0.7f * mg.y * u1.y + CF * ai1;
    outim.z = 0.7f * mg.z * u2.y + CF * ai2;
    outim.w = 0.7f * mg.w * u3.y + CF * ai3;

    *(float4*)(g_new_re + base) = outre;
    *(float4*)(g_new_im + base) = outim;
}

// ---------------- K4: emission ----------------
__global__ void __launch_bounds__(128) k_emit() {
    int t = threadIdx.x;
    int c0 = blockIdx.x * 64;
    float sr0 = 0, sr1 = 0, sr2 = 0, sr3 = 0, si0 = 0, si1 = 0, si2 = 0, si3 = 0;
    for (int c = 0; c < 64; c++) {
        int cell = c0 + c;
        if (g_lasing[cell]) {
            size_t base = (size_t)cell * H + (size_t)t * 4;
            float4 r = *(const float4*)(g_new_re + base);
            float4 i = *(const float4*)(g_new_im + base);
            sr0 += r.x; sr1 += r.y; sr2 += r.z; sr3 += r.w;
            si0 += i.x; si1 += i.y; si2 += i.z; si3 += i.w;
        }
    }
    int h = t * 4;
    atomicAdd(&g_em_re[h + 0], sr0); atomicAdd(&g_em_re[h + 1], sr1);
    atomicAdd(&g_em_re[h + 2], sr2); atomicAdd(&g_em_re[h + 3], sr3);
    atomicAdd(&g_em_im[h + 0], si0); atomicAdd(&g_em_im[h + 1], si1);
    atomicAdd(&g_em_im[h + 2], si2); atomicAdd(&g_em_im[h + 3], si3);
}

// ---------------- K5a: cavity update ----------------
__global__ void __launch_bounds__(512) k_cav_update(const float* __restrict__ cav_re,
                                                    const float* __restrict__ cav_im) {
    int t = threadIdx.x;
    int nl = g_nlasing;
    float inv = 1.f / fmaxf((float)nl, 1.f);
    float cr = cav_re[t], ci = cav_im[t];
    float nr = (nl > 0) ? 0.8f * cr + 0.2f * (g_em_re[t] * inv) : cr;
    float ni = (nl > 0) ? 0.8f * ci + 0.2f * (g_em_im[t] * inv) : ci;
    g_cavn_re[t] = nr;
    g_cavn_im[t] = ni;
    g_cav_phase[t] = atan2f(ci, cr);   // OLD cavity phase
}

// ---------------- K5b: decode GEMV ----------------
__global__ void __launch_bounds__(128) k_decode(const float* __restrict__ decW,
                                                const float* __restrict__ decb,
                                                float* __restrict__ out) {
    int d = blockIdx.x;
    int t = threadIdx.x;
    const float* w = decW + (size_t)d * (2 * H);
    float s = 0.f;
#pragma unroll
    for (int j = t; j < 2 * H; j += 128) {
        float v = (j < H) ? g_cavn_re[j] : g_cavn_im[j - H];
        s = fmaf(v, w[j], s);
    }
#pragma unroll
    for (int o = 16; o; o >>= 1) s += __shfl_xor_sync(0xFFFFFFFFu, s, o);
    __shared__ float red[4];
    if ((t & 31) == 0) red[t >> 5] = s;
    __syncthreads();
    if (t == 0) out[d] = red[0] + red[1] + red[2] + red[3] + decb[d];
}

// ---------------- K6: finalize + variance ----------------
__global__ void __launch_bounds__(128) k_final() {
    int cell = blockIdx.x;
    int t = threadIdx.x;
    __shared__ float red[128];
    __shared__ float rs[128], rs2[128];

    size_t base = (size_t)cell * H + (size_t)t * 4;
    float4 r4 = *(const float4*)(g_new_re + base);
    float4 i4 = *(const float4*)(g_new_im + base);
    int las = g_lasing[cell];

    float amp[4];
    float re_[4] = {r4.x, r4.y, r4.z, r4.w};
    float im_[4] = {i4.x, i4.y, i4.z, i4.w};
    float mx = 0.f;
#pragma unroll
    for (int q = 0; q < 4; q++) {
        int h = t * 4 + q;
        float re = re_[q], im = im_[q];
        if (las) {
            float a = sqrtf(re * re + im * im);
            float ang = 0.3f * g_cav_phase[h] + 0.7f * atan2f(im, re);
            float sn, cs;
            __sincosf(ang, &sn, &cs);
            re = a * cs;
            im = a * sn;
        }
        re += 0.05f * g_cavn_re[h];
        im += 0.05f * g_cavn_im[h];
        amp[q] = sqrtf(re * re + im * im);
        mx = fmaxf(mx, amp[q]);
    }
    red[t] = mx;
    __syncthreads();
#pragma unroll
    for (int o = 64; o; o >>= 1) {
        if (t < o) red[t] = fmaxf(red[t], red[t + o]);
        __syncthreads();
    }
    float inv = 1.f / (red[0] + 1e-8f);
    float s = 0.f, s2 = 0.f;
#pragma unroll
    for (int q = 0; q < 4; q++) {
        float an = amp[q] * inv;
        s += an;
        s2 = fmaf(an, an, s2);
    }
    rs[t] = s; rs2[t] = s2;
    __syncthreads();
#pragma unroll
    for (int o = 64; o; o >>= 1) {
        if (t < o) { rs[t] += rs[t + o]; rs2[t] += rs2[t + o]; }
        __syncthreads();
    }
    if (t == 0) {
        atomicAdd(&g_sum,  (double)rs[0]);
        atomicAdd(&g_sum2, (double)rs2[0]);
    }
}

// ---------------- K7: tension ----------------
__global__ void k_tension(float* __restrict__ out, int out_size) {
    double M = (double)N_CELLS * (double)H;
    double mean = g_sum / M;
    double var = g_sum2 / M - mean * mean;
    out[out_size - 1] = (float)var;
}

// ---------------- launcher ----------------
extern "C" void kernel_launch(void* const* d_in, const int* in_sizes, int n_in,
                              void* d_out, int out_size) {
    const float* x       = (const float*)d_in[0];
    const float* pump_W  = (const float*)d_in[1];
    const float* pump_b  = (const float*)d_in[2];
    const float* dec_W   = (const float*)d_in[3];
    const float* dec_b   = (const float*)d_in[4];
    const float* cs_re   = (const float*)d_in[5];
    const float* cs_im   = (const float*)d_in[6];
    const float* excited = (const float*)d_in[7];
    const float* phase_v = (const float*)d_in[8];
    const float* cav_re  = (const float*)d_in[9];
    const float* cav_im  = (const float*)d_in[10];
    const int*   nbr     = (const int*)d_in[11];
    float* out = (float*)d_out;

    k_init<<<1, H>>>();
    k_pump<<<(N_CELLS * 32) / 256, 256>>>(x, pump_W, pump_b, excited);
    k_rot<<<(N_CELLS * H) / 256, 256>>>(cs_re, cs_im, phase_v);
    k_couple<<<N_CELLS, 128>>>(nbr);
    k_emit<<<N_CELLS / 64, 128>>>();
    k_cav_update<<<1, 512>>>(cav_re, cav_im);
    k_decode<<<D, 128>>>(dec_W, dec_b, out);
    k_final<<<N_CELLS, 128>>>();
    k_tension<<<1, 1>>>(out, out_size);
}

// round 4
// speedup vs baseline: 3.1249x; 1.1557x over previous
#include <cuda_runtime.h>
#include <cuda_fp16.h>
#include <math.h>
#include <stdint.h>

#define N_CELLS 16384
#define H 512
#define D 512
#define KNB 15

// ---------------- scratch ----------------
// v = sqrt(|s|) * unit(s)  packed half2 (re,im). Everything k_couple needs.
__device__ __half2 g_v  [N_CELLS * H];
__device__ __half2 g_new[N_CELLS * H];   // new_states packed (re,im)
__device__ int    g_lasing[N_CELLS];
__device__ int    g_nlasing;
__device__ float  g_em_re[H];
__device__ float  g_em_im[H];
__device__ float  g_cavn_re[H];
__device__ float  g_cavn_im[H];
__device__ float  g_cav_phase[H];
__device__ double g_sum, g_sum2;

// ---------------- K0 ----------------
__global__ void k_init() {
    int t = threadIdx.x;
    if (t < H) { g_em_re[t] = 0.f; g_em_im[t] = 0.f; }
    if (t == 0) { g_nlasing = 0; g_sum = 0.0; g_sum2 = 0.0; }
}

// ---------------- K1: pump -> lasing ----------------
__global__ void k_pump(const float* __restrict__ x,
                       const float* __restrict__ W,
                       const float* __restrict__ b,
                       const float* __restrict__ excited) {
    int gwarp = (blockIdx.x * blockDim.x + threadIdx.x) >> 5;
    int lane  = threadIdx.x & 31;
    if (gwarp >= N_CELLS) return;
    const float* w = W + (size_t)gwarp * D;
    float s = 0.f;
#pragma unroll
    for (int t = 0; t < D / 32; t++)
        s += x[lane + 32 * t] * w[lane + 32 * t];
#pragma unroll
    for (int o = 16; o; o >>= 1) s += __shfl_xor_sync(0xFFFFFFFFu, s, o);
    if (lane == 0) {
        float z = s + b[gwarp];
        float pump = 1.f / (1.f + expf(-z));
        float e = excited[gwarp] * 0.95f + pump * 0.05f;
        e = fminf(fmaxf(e, 0.f), 1.f);
        int las = (e > 0.5f) ? 1 : 0;
        g_lasing[gwarp] = las;
        if (las) atomicAdd(&g_nlasing, 1);
    }
}

// ---------------- K2: rotate + scale to v = s / sqrt(|s|) ----------------
__global__ void k_rot(const float* __restrict__ cr,
                      const float* __restrict__ ci,
                      const float* __restrict__ pv) {
    int i = blockIdx.x * blockDim.x + threadIdx.x;
    if (i >= N_CELLS * H) return;
    float sn, cs;
    __sincosf(0.1f * pv[i], &sn, &cs);
    float a = cr[i], b = ci[i];
    float re = a * cs - b * sn;
    float im = a * sn + b * cs;
    float m2 = fmaxf(re * re + im * im, 1e-30f);   // = |s|^2
    float q = rsqrtf(sqrtf(m2));                   // = |s|^(-1/2)
    g_v[i] = __floats2half2_rn(re * q, im * q);    // |v| = sqrt(|s|)
}

// ---------------- K3: neighbor coupling (hot) ----------------
// cos(ang_i-ang_j)*m_j*u_j = (v_i . v_j) * v_j / |v_i| ;  0.7*s_i = 0.7*|v_i|*v_i
__global__ void __launch_bounds__(128) k_couple(const int* __restrict__ nbr) {
    int cell = blockIdx.x;
    int t = threadIdx.x;
    __shared__ int snb[KNB];
    if (t < KNB) snb[t] = nbr[cell * KNB + t];
    __syncthreads();

    size_t base = (size_t)cell * H + (size_t)t * 4;

    uint4 vp = *(const uint4*)(g_v + base);
    float2 v0 = __half22float2(*(const __half2*)&vp.x);
    float2 v1 = __half22float2(*(const __half2*)&vp.y);
    float2 v2 = __half22float2(*(const __half2*)&vp.z);
    float2 v3 = __half22float2(*(const __half2*)&vp.w);

    float ar0 = 0.f, ar1 = 0.f, ar2 = 0.f, ar3 = 0.f;
    float ai0 = 0.f, ai1 = 0.f, ai2 = 0.f, ai3 = 0.f;

#pragma unroll 3
    for (int j = 0; j < KNB; j++) {
        size_t nb = (size_t)snb[j] * H + (size_t)t * 4;
        uint4 np = *(const uint4*)(g_v + nb);
        float2 n0 = __half22float2(*(const __half2*)&np.x);
        float2 n1 = __half22float2(*(const __half2*)&np.y);
        float2 n2 = __half22float2(*(const __half2*)&np.z);
        float2 n3 = __half22float2(*(const __half2*)&np.w);

        float d;
        d = fmaf(v0.x, n0.x, v0.y * n0.y);
        ar0 = fmaf(d, n0.x, ar0); ai0 = fmaf(d, n0.y, ai0);
        d = fmaf(v1.x, n1.x, v1.y * n1.y);
        ar1 = fmaf(d, n1.x, ar1); ai1 = fmaf(d, n1.y, ai1);
        d = fmaf(v2.x, n2.x, v2.y * n2.y);
        ar2 = fmaf(d, n2.x, ar2); ai2 = fmaf(d, n2.y, ai2);
        d = fmaf(v3.x, n3.x, v3.y * n3.y);
        ar3 = fmaf(d, n3.x, ar3); ai3 = fmaf(d, n3.y, ai3);
    }

    const float CF = 0.3f * 0.1f / (float)KNB;  // 0.002
    float a2, inv, amp;
    uint4 outp;

    a2 = fmaxf(fmaf(v0.x, v0.x, v0.y * v0.y), 1e-30f);
    inv = rsqrtf(a2); amp = a2 * inv;
    *(__half2*)&outp.x = __floats2half2_rn(0.7f * amp * v0.x + CF * inv * ar0,
                                           0.7f * amp * v0.y + CF * inv * ai0);
    a2 = fmaxf(fmaf(v1.x, v1.x, v1.y * v1.y), 1e-30f);
    inv = rsqrtf(a2); amp = a2 * inv;
    *(__half2*)&outp.y = __floats2half2_rn(0.7f * amp * v1.x + CF * inv * ar1,
                                           0.7f * amp * v1.y + CF * inv * ai1);
    a2 = fmaxf(fmaf(v2.x, v2.x, v2.y * v2.y), 1e-30f);
    inv = rsqrtf(a2); amp = a2 * inv;
    *(__half2*)&outp.z = __floats2half2_rn(0.7f * amp * v2.x + CF * inv * ar2,
                                           0.7f * amp * v2.y + CF * inv * ai2);
    a2 = fmaxf(fmaf(v3.x, v3.x, v3.y * v3.y), 1e-30f);
    inv = rsqrtf(a2); amp = a2 * inv;
    *(__half2*)&outp.w = __floats2half2_rn(0.7f * amp * v3.x + CF * inv * ar3,
                                           0.7f * amp * v3.y + CF * inv * ai3);

    *(uint4*)(g_new + base) = outp;
}

// ---------------- K4: emission ----------------
__global__ void __launch_bounds__(128) k_emit() {
    int t = threadIdx.x;
    int c0 = blockIdx.x * 64;
    float sr0 = 0, sr1 = 0, sr2 = 0, sr3 = 0, si0 = 0, si1 = 0, si2 = 0, si3 = 0;
    for (int c = 0; c < 64; c++) {
        int cell = c0 + c;
        if (g_lasing[cell]) {
            size_t base = (size_t)cell * H + (size_t)t * 4;
            uint4 p = *(const uint4*)(g_new + base);
            float2 c0v = __half22float2(*(const __half2*)&p.x);
            float2 c1v = __half22float2(*(const __half2*)&p.y);
            float2 c2v = __half22float2(*(const __half2*)&p.z);
            float2 c3v = __half22float2(*(const __half2*)&p.w);
            sr0 += c0v.x; si0 += c0v.y;
            sr1 += c1v.x; si1 += c1v.y;
            sr2 += c2v.x; si2 += c2v.y;
            sr3 += c3v.x; si3 += c3v.y;
        }
    }
    int h = t * 4;
    atomicAdd(&g_em_re[h + 0], sr0); atomicAdd(&g_em_re[h + 1], sr1);
    atomicAdd(&g_em_re[h + 2], sr2); atomicAdd(&g_em_re[h + 3], sr3);
    atomicAdd(&g_em_im[h + 0], si0); atomicAdd(&g_em_im[h + 1], si1);
    atomicAdd(&g_em_im[h + 2], si2); atomicAdd(&g_em_im[h + 3], si3);
}

// ---------------- K5a: cavity update ----------------
__global__ void __launch_bounds__(512) k_cav_update(const float* __restrict__ cav_re,
                                                    const float* __restrict__ cav_im) {
    int t = threadIdx.x;
    int nl = g_nlasing;
    float inv = 1.f / fmaxf((float)nl, 1.f);
    float cr = cav_re[t], ci = cav_im[t];
    float nr = (nl > 0) ? 0.8f * cr + 0.2f * (g_em_re[t] * inv) : cr;
    float ni = (nl > 0) ? 0.8f * ci + 0.2f * (g_em_im[t] * inv) : ci;
    g_cavn_re[t] = nr;
    g_cavn_im[t] = ni;
    g_cav_phase[t] = atan2f(ci, cr);   // OLD cavity phase
}

// ---------------- K5b: decode GEMV ----------------
__global__ void __launch_bounds__(128) k_decode(const float* __restrict__ decW,
                                                const float* __restrict__ decb,
                                                float* __restrict__ out) {
    int d = blockIdx.x;
    int t = threadIdx.x;
    const float* w = decW + (size_t)d * (2 * H);
    float s = 0.f;
#pragma unroll
    for (int j = t; j < 2 * H; j += 128) {
        float v = (j < H) ? g_cavn_re[j] : g_cavn_im[j - H];
        s = fmaf(v, w[j], s);
    }
#pragma unroll
    for (int o = 16; o; o >>= 1) s += __shfl_xor_sync(0xFFFFFFFFu, s, o);
    __shared__ float red[4];
    if ((t & 31) == 0) red[t >> 5] = s;
    __syncthreads();
    if (t == 0) out[d] = red[0] + red[1] + red[2] + red[3] + decb[d];
}

// ---------------- K6: finalize + variance ----------------
__global__ void __launch_bounds__(128) k_final() {
    int cell = blockIdx.x;
    int t = threadIdx.x;
    __shared__ float red[128];
    __shared__ float rs[128], rs2[128];

    size_t base = (size_t)cell * H + (size_t)t * 4;
    uint4 p = *(const uint4*)(g_new + base);
    float2 c0 = __half22float2(*(const __half2*)&p.x);
    float2 c1 = __half22float2(*(const __half2*)&p.y);
    float2 c2 = __half22float2(*(const __half2*)&p.z);
    float2 c3 = __half22float2(*(const __half2*)&p.w);
    int las = g_lasing[cell];

    float amp[4];
    float re_[4] = {c0.x, c1.x, c2.x, c3.x};
    float im_[4] = {c0.y, c1.y, c2.y, c3.y};
    float mx = 0.f;
#pragma unroll
    for (int q = 0; q < 4; q++) {
        int h = t * 4 + q;
        float re = re_[q], im = im_[q];
        if (las) {
            float a = sqrtf(re * re + im * im);
            float ang = 0.3f * g_cav_phase[h] + 0.7f * atan2f(im, re);
            float sn, cs;
            __sincosf(ang, &sn, &cs);
            re = a * cs;
            im = a * sn;
        }
        re += 0.05f * g_cavn_re[h];
        im += 0.05f * g_cavn_im[h];
        amp[q] = sqrtf(re * re + im * im);
        mx = fmaxf(mx, amp[q]);
    }
    red[t] = mx;
    __syncthreads();
#pragma unroll
    for (int o = 64; o; o >>= 1) {
        if (t < o) red[t] = fmaxf(red[t], red[t + o]);
        __syncthreads();
    }
    float inv = 1.f / (red[0] + 1e-8f);
    float s = 0.f, s2 = 0.f;
#pragma unroll
    for (int q = 0; q < 4; q++) {
        float an = amp[q] * inv;
        s += an;
        s2 = fmaf(an, an, s2);
    }
    rs[t] = s; rs2[t] = s2;
    __syncthreads();
#pragma unroll
    for (int o = 64; o; o >>= 1) {
        if (t < o) { rs[t] += rs[t + o]; rs2[t] += rs2[t + o]; }
        __syncthreads();
    }
    if (t == 0) {
        atomicAdd(&g_sum,  (double)rs[0]);
        atomicAdd(&g_sum2, (double)rs2[0]);
    }
}

// ---------------- K7: tension ----------------
__global__ void k_tension(float* __restrict__ out, int out_size) {
    double M = (double)N_CELLS * (double)H;
    double mean = g_sum / M;
    double var = g_sum2 / M - mean * mean;
    out[out_size - 1] = (float)var;
}

// ---------------- launcher ----------------
extern "C" void kernel_launch(void* const* d_in, const int* in_sizes, int n_in,
                              void* d_out, int out_size) {
    const float* x       = (const float*)d_in[0];
    const float* pump_W  = (const float*)d_in[1];
    const float* pump_b  = (const float*)d_in[2];
    const float* dec_W   = (const float*)d_in[3];
    const float* dec_b   = (const float*)d_in[4];
    const float* cs_re   = (const float*)d_in[5];
    const float* cs_im   = (const float*)d_in[6];
    const float* excited = (const float*)d_in[7];
    const float* phase_v = (const float*)d_in[8];
    const float* cav_re  = (const float*)d_in[9];
    const float* cav_im  = (const float*)d_in[10];
    const int*   nbr     = (const int*)d_in[11];
    float* out = (float*)d_out;

    k_init<<<1, H>>>();
    k_pump<<<(N_CELLS * 32) / 256, 256>>>(x, pump_W, pump_b, excited);
    k_rot<<<(N_CELLS * H) / 256, 256>>>(cs_re, cs_im, phase_v);
    k_couple<<<N_CELLS, 128>>>(nbr);
    k_emit<<<N_CELLS / 64, 128>>>();
    k_cav_update<<<1, 512>>>(cav_re, cav_im);
    k_decode<<<D, 128>>>(dec_W, dec_b, out);
    k_final<<<N_CELLS, 128>>>();
    k_tension<<<1, 1>>>(out, out_size);
}